// round 13
// baseline (speedup 1.0000x reference)
#include <cuda_runtime.h>
#include <cuda_fp16.h>
#include <math.h>
#include <stdint.h>

#define NODECAP 16384
#define G_TOTAL 237568   // 192*384 + 256*512 + 128*256
#define PRECAP  (1<<20)
#define SMEM_BYTES 114688   // 64KB A frags + 48KB per-warp B rings (8 x 3 x 2KB)

// Prepped fragment-major fp16 weights: [0]=q [1]=k
__device__ __align__(16) __half g_B[2][G_TOTAL];
__device__ float    g_pre[PRECAP];
__device__ unsigned g_segmax[NODECAP * 8];
__device__ float    g_segsum[NODECAP * 8];

__constant__ int c_ord[9] = {0, 2, 6, 3, 7, 1, 5, 8, 4};
__constant__ int c_KT[3]  = {12, 16, 8};
__constant__ int c_NPJ[3] = {3, 4, 2};          // NP / 8
__constant__ int c_D[3]   = {192, 256, 128};
__constant__ int c_IB0[3] = {0, 3, 7};
__constant__ int c_B4[3]  = {0, 9216, 25600};   // uint4 base per group

// ---------------------------------------------------------------------------
// Weight prep: dense W_eff per |m| group (sign pattern folded), fp16,
// exact mma.m16n8k16 B-fragment order. Blocks are (j,kt)-MAJOR and
// contiguous: per warp-step the cursor just advances 256 uint4.
// ---------------------------------------------------------------------------
__global__ void prep_w(const float* __restrict__ W, int mat) {
    int idx = blockIdx.x * blockDim.x + threadIdx.x;
    if (idx >= G_TOTAL) return;
    int g, kk, n, KT, boff, rem = idx;
    if (rem < 73728)       { g = 0; kk = rem / 384; n = rem % 384; KT = 12; boff = 0; }
    else if (rem < 204800) { rem -= 73728;  g = 1; kk = rem / 512; n = rem % 512; KT = 16; boff = 73728; }
    else                   { rem -= 204800; g = 2; kk = rem / 256; n = rem % 256; KT = 8;  boff = 204800; }

    int c = kk & 63, d = n & 127, ib = kk >> 6, ob = n >> 7;
    int w; float s = 1.0f;
    if (g == 0) {
        w = ib * 3 + ob;
    } else if (g == 1) {
        int i = ib & 1, o = ob & 1;
        bool ip = ib < 2, op = ob < 2;
        int base = 9 + i * 4 + o * 2;
        if (ip && op)        w = base;                   // +Wr
        else if (!ip && op)  { w = base + 1; s = -1.f; } // -Wi
        else if (ip && !op)  w = base + 1;               // +Wi
        else                 w = base;                   // +Wr
    } else {
        bool ip = (ib == 0), op = (ob == 0);
        if (ip && op)        w = 17;
        else if (!ip && op)  { w = 18; s = -1.f; }
        else if (ip && !op)  w = 18;
        else                 w = 17;
    }
    int widx = (w * 64 + c) * 128 + d;

    int kt = kk >> 4, k16 = kk & 15, n8 = n >> 3;
    int lane = (n & 7) * 4 + ((k16 & 7) >> 1);
    int slot = (k16 & 1) + ((k16 >> 3) << 1);
    int P = n8 >> 1, j = P >> 3, pp = P & 7;
    int blk = j * KT + kt;   // sequential step index within group
    int off = boff + ((blk * 8 + pp) * 32 + lane) * 8 + ((n8 & 1) << 2) + slot;

    g_B[mat][off] = __float2half(s * W[widx]);
}

// ---------------------------------------------------------------------------
__device__ __forceinline__ uint32_t s2u(const void* p) {
    uint32_t a;
    asm("{ .reg .u64 t; cvta.to.shared.u64 t, %1; cvt.u32.u64 %0, t; }" : "=r"(a) : "l"(p));
    return a;
}
#define CPA16(d, sp)  asm volatile("cp.async.cg.shared.global [%0], [%1], 16;" :: "r"(d), "l"(sp) : "memory")
#define CPA_COMMIT()  asm volatile("cp.async.commit_group;" ::: "memory")
#define CPA_WAIT0()   asm volatile("cp.async.wait_group 0;" ::: "memory")
#define CPA_WAIT1()   asm volatile("cp.async.wait_group 1;" ::: "memory")
#define CPA_WAIT2()   asm volatile("cp.async.wait_group 2;" ::: "memory")

#define MMA(c, a0, a1, a2, a3, b0, b1) asm volatile( \
    "mma.sync.aligned.m16n8k16.row.col.f32.f16.f16.f32 " \
    "{%0,%1,%2,%3},{%4,%5,%6,%7},{%8,%9},{%0,%1,%2,%3};\n" \
    : "+f"((c)[0]), "+f"((c)[1]), "+f"((c)[2]), "+f"((c)[3]) \
    : "r"(a0), "r"(a1), "r"(a2), "r"(a3), "r"(b0), "r"(b1))

#define MMA4(c, a, b0, b1) MMA(c, (a).x, (a).y, (a).z, (a).w, b0, b1)

__global__ __launch_bounds__(256, 2)
void so2_attn_main(const float* __restrict__ xq, const float* __restrict__ xk, int E) {
    extern __shared__ __half sA[];   // [0]=q frags (16384 halfs), [16384]=k frags
    uint4* sB = (uint4*)(sA + 32768);        // per-warp rings: warp*384 + slot*128 uint4
    const int tid = threadIdx.x, lane = tid & 31, warp = tid >> 5;
    const int warpM = warp & 1, warpN = warp >> 1;
    const int tileE = blockIdx.x * 64;
    const uint32_t wring_u32 = s2u(sB) + ((warp * 384 + lane) << 4);
    const uint4* wring = sB + warp * 384;

    float pre[2][2][2];   // [mt][rowhalf][np] ; head = warpN + np*4
    #pragma unroll
    for (int a = 0; a < 2; a++)
        #pragma unroll
        for (int b = 0; b < 2; b++)
            #pragma unroll
            for (int c = 0; c < 2; c++) pre[a][b][c] = 0.f;

    for (int g = 0; g < 3; ++g) {
        const int Kt = c_KT[g], NPJ = c_NPJ[g], D = c_D[g];
        __syncthreads();   // previous group's compute fully done before rewriting sA
        // ---- convert x slice -> fragment-major fp16 smem (64 edges) ----
        const int nq = 64 * (D >> 2);
        #pragma unroll
        for (int t = 0; t < 2; ++t) {
            const float* x = t ? xk : xq;
            __half* A = sA + t * 16384;
            for (int q0 = tid; q0 < nq; q0 += 256) {
                int el = q0 / (D >> 2), c = (q0 % (D >> 2)) * 4;
                int ord = c_ord[c_IB0[g] + (c >> 6)];
                int e = tileE + el;
                float4 v = make_float4(0.f, 0.f, 0.f, 0.f);
                if (e < E) v = *(const float4*)(x + ((size_t)e * 9 + ord) * 64 + (c & 63));
                int r = el & 15, mtile = el >> 4;
                int kt = c >> 4, kk0 = c & 15;
                int ln0 = (r & 7) * 4 + ((kk0 & 7) >> 1);
                int hx  = (((kk0 >> 3) << 1) + (r >> 3)) * 2;
                int off = ((mtile * Kt + kt) * 32 + ln0) * 8 + hx;
                *(__half2*)(A + off)     = __floats2half2_rn(v.x, v.y);
                *(__half2*)(A + off + 8) = __floats2half2_rn(v.z, v.w);
            }
        }
        __syncthreads();

        // ---- fused fp16 GEMMs + per-head q*k reduction ----
        // Per-warp private 3-stage cp.async ring; sequential B cursor
        // (ptr += 256/step); A fragments register-rotated one kt ahead.
        const uint4* Aq = (const uint4*)sA;
        const uint4* Ak = Aq + 2048;
        const int S = NPJ * Kt, Sm2 = S - 2;

        const uint4* pq = (const uint4*)g_B[0] + c_B4[g] + warpN * 32 + lane;
        const uint4* pk = (const uint4*)g_B[1] + c_B4[g] + warpN * 32 + lane;

        #define ISSUE_W(slot_) do { \
            uint32_t _d = wring_u32 + (uint32_t)((slot_) << 11); \
            CPA16(_d,        pq); \
            CPA16(_d + 512,  pq + 128); \
            CPA16(_d + 1024, pk); \
            CPA16(_d + 1536, pk + 128); \
            CPA_COMMIT(); \
            pq += 256; pk += 256; \
        } while (0)

        ISSUE_W(0); ISSUE_W(1); ISSUE_W(2);

        int s = 0, slot = 0;
        for (int j = 0; j < NPJ; ++j) {
            float cq[2][2][2][4], ck[2][2][2][4];   // [np][mt][d2][4]
            #pragma unroll
            for (int a = 0; a < 2; a++)
                #pragma unroll
                for (int b = 0; b < 2; b++)
                    #pragma unroll
                    for (int d2 = 0; d2 < 2; d2++)
                        #pragma unroll
                        for (int i = 0; i < 4; i++) { cq[a][b][d2][i] = 0.f; ck[a][b][d2][i] = 0.f; }

            // per-warp A base pointers for its two m-tiles
            const uint4* a0 = Aq + (2 * warpM) * Kt * 32 + lane;
            const uint4* a1 = a0 + Kt * 32;
            const uint4* k0 = Ak + (2 * warpM) * Kt * 32 + lane;
            const uint4* k1 = k0 + Kt * 32;

            // A prologue: kt=0 fragments
            uint4 aqc0 = a0[0], aqc1 = a1[0], akc0 = k0[0], akc1 = k1[0];

            #pragma unroll 1
            for (int kt = 0; kt < Kt; ++kt, ++s) {
                if (s < Sm2) CPA_WAIT2();
                else if (s == Sm2) CPA_WAIT1();
                else CPA_WAIT0();

                const uint4* slotp = wring + (slot << 7);
                uint4 bq0 = slotp[lane],      bq1 = slotp[32 + lane];
                uint4 bk0 = slotp[64 + lane], bk1 = slotp[96 + lane];

                if (s + 3 < S) ISSUE_W(slot);

                // rotate A: load kt+1 (clamped) while MMAs consume kt
                int noff = (kt + 1 < Kt) ? (kt + 1) * 32 : kt * 32;
                uint4 aqn0 = a0[noff], aqn1 = a1[noff];
                uint4 akn0 = k0[noff], akn1 = k1[noff];

                MMA4(cq[0][0][0], aqc0, bq0.x, bq0.y);
                MMA4(cq[0][0][1], aqc0, bq0.z, bq0.w);
                MMA4(cq[0][1][0], aqc1, bq0.x, bq0.y);
                MMA4(cq[0][1][1], aqc1, bq0.z, bq0.w);
                MMA4(cq[1][0][0], aqc0, bq1.x, bq1.y);
                MMA4(cq[1][0][1], aqc0, bq1.z, bq1.w);
                MMA4(cq[1][1][0], aqc1, bq1.x, bq1.y);
                MMA4(cq[1][1][1], aqc1, bq1.z, bq1.w);
                MMA4(ck[0][0][0], akc0, bk0.x, bk0.y);
                MMA4(ck[0][0][1], akc0, bk0.z, bk0.w);
                MMA4(ck[0][1][0], akc1, bk0.x, bk0.y);
                MMA4(ck[0][1][1], akc1, bk0.z, bk0.w);
                MMA4(ck[1][0][0], akc0, bk1.x, bk1.y);
                MMA4(ck[1][0][1], akc0, bk1.z, bk1.w);
                MMA4(ck[1][1][0], akc1, bk1.x, bk1.y);
                MMA4(ck[1][1][1], akc1, bk1.z, bk1.w);

                aqc0 = aqn0; aqc1 = aqn1; akc0 = akn0; akc1 = akn1;
                if (++slot == 3) slot = 0;
            }
            #pragma unroll
            for (int np = 0; np < 2; ++np)
                #pragma unroll
                for (int mt = 0; mt < 2; ++mt) {
                    pre[mt][0][np] += cq[np][mt][0][0] * ck[np][mt][0][0] + cq[np][mt][0][1] * ck[np][mt][0][1]
                                    + cq[np][mt][1][0] * ck[np][mt][1][0] + cq[np][mt][1][1] * ck[np][mt][1][1];
                    pre[mt][1][np] += cq[np][mt][0][2] * ck[np][mt][0][2] + cq[np][mt][0][3] * ck[np][mt][0][3]
                                    + cq[np][mt][1][2] * ck[np][mt][1][2] + cq[np][mt][1][3] * ck[np][mt][1][3];
                }
        }
        #undef ISSUE_W
    }

    // reduce over the 4-lane n-split group and store pre (unique writer per (e,h))
    #pragma unroll
    for (int a = 0; a < 2; a++)
        #pragma unroll
        for (int b = 0; b < 2; b++)
            #pragma unroll
            for (int c = 0; c < 2; c++) {
                float v = pre[a][b][c];
                v += __shfl_xor_sync(0xffffffffu, v, 1);
                v += __shfl_xor_sync(0xffffffffu, v, 2);
                pre[a][b][c] = v;
            }
    if ((lane & 3) == 0) {
        int gID = lane >> 2;
        #pragma unroll
        for (int mt = 0; mt < 2; ++mt)
            #pragma unroll
            for (int rh = 0; rh < 2; ++rh)
                #pragma unroll
                for (int np = 0; np < 2; ++np) {
                    int e = tileE + (2 * warpM + mt) * 16 + gID + rh * 8;
                    int h = warpN + np * 4;
                    if (e < E) g_pre[e * 8 + h] = 0.25f * pre[mt][rh][np];
                }
    }
}

// ---------------------------------------------------------------------------
// Segment softmax
// ---------------------------------------------------------------------------
__device__ __forceinline__ unsigned fenc(float f) {
    unsigned b = __float_as_uint(f);
    return (b & 0x80000000u) ? ~b : (b | 0x80000000u);
}
__device__ __forceinline__ float fdec(unsigned u) {
    unsigned b = (u & 0x80000000u) ? (u & 0x7FFFFFFFu) : ~u;
    return __uint_as_float(b);
}

__global__ void k_init() {
    int i = blockIdx.x * blockDim.x + threadIdx.x;
    if (i < NODECAP * 8) { g_segmax[i] = 0u; g_segsum[i] = 0.f; }
}
__global__ void k_max(int E, const int* __restrict__ index) {
    int i = blockIdx.x * blockDim.x + threadIdx.x;
    if (i >= E * 8) return;
    int e = i >> 3, h = i & 7;
    atomicMax(&g_segmax[index[e] * 8 + h], fenc(g_pre[i]));
}
__global__ void k_exp(int E, const int* __restrict__ index, float* __restrict__ out) {
    int i = blockIdx.x * blockDim.x + threadIdx.x;
    if (i >= E * 8) return;
    int e = i >> 3, h = i & 7;
    int seg = index[e] * 8 + h;
    float ex = expf(g_pre[i] - fdec(g_segmax[seg]));
    out[i] = ex;
    atomicAdd(&g_segsum[seg], ex);
}
__global__ void k_norm(int E, const int* __restrict__ index, float* __restrict__ out) {
    int i = blockIdx.x * blockDim.x + threadIdx.x;
    if (i >= E * 8) return;
    int e = i >> 3, h = i & 7;
    out[i] = out[i] / (g_segsum[index[e] * 8 + h] + 1e-16f);
}

// ---------------------------------------------------------------------------
extern "C" void kernel_launch(void* const* d_in, const int* in_sizes, int n_in,
                              void* d_out, int out_size) {
    const float* xq    = (const float*)d_in[0];
    const float* xk    = (const float*)d_in[1];
    const float* Wq    = (const float*)d_in[2];
    const float* Wk    = (const float*)d_in[3];
    const int*   index = (const int*)d_in[4];
    float* out = (float*)d_out;
    int E = in_sizes[0] / (9 * 64);

    cudaFuncSetAttribute(so2_attn_main, cudaFuncAttributeMaxDynamicSharedMemorySize, SMEM_BYTES);

    // our launch idx 3 == global idx 5 (2 hidden harness launches) for ncu -s 5 -c 1
    prep_w<<<(G_TOTAL + 255) / 256, 256>>>(Wq, 0);
    prep_w<<<(G_TOTAL + 255) / 256, 256>>>(Wk, 1);
    k_init<<<(NODECAP * 8 + 255) / 256, 256>>>();

    so2_attn_main<<<(E + 63) / 64, 256, SMEM_BYTES>>>(xq, xk, E);

    int nb = (E * 8 + 255) / 256;
    k_max <<<nb, 256>>>(E, index);
    k_exp <<<nb, 256>>>(E, index, out);
    k_norm<<<nb, 256>>>(E, index, out);
}

// round 14
// speedup vs baseline: 1.3345x; 1.3345x over previous
#include <cuda_runtime.h>
#include <cuda_fp16.h>
#include <math.h>
#include <stdint.h>

#define NODECAP 16384
#define G_TOTAL 237568   // 192*384 + 256*512 + 128*256
#define BPAD    8192     // overrun pad: 3 steps x 256 uint4 x 8 halfs + slack
#define PRECAP  (1<<20)
#define SMEM_BYTES 114688   // 64KB A frags + 48KB per-warp B rings (8 x 3 x 2KB)

// Prepped fragment-major fp16 weights (padded for unconditional cursor overrun)
__device__ __align__(16) __half g_Bq[G_TOTAL + BPAD];
__device__ __align__(16) __half g_Bk[G_TOTAL + BPAD];
__device__ float    g_pre[PRECAP];
__device__ unsigned g_segmax[NODECAP * 8];
__device__ float    g_segsum[NODECAP * 8];

__constant__ int c_ord[9] = {0, 2, 6, 3, 7, 1, 5, 8, 4};

// ---------------------------------------------------------------------------
// Weight prep: dense W_eff per |m| group (sign pattern folded), fp16,
// exact mma.m16n8k16 B-fragment order, (j,kt)-major contiguous blocks.
// ---------------------------------------------------------------------------
__global__ void prep_w(const float* __restrict__ W, __half* __restrict__ dst) {
    int idx = blockIdx.x * blockDim.x + threadIdx.x;
    if (idx >= G_TOTAL) return;
    int g, kk, n, KT, boff, rem = idx;
    if (rem < 73728)       { g = 0; kk = rem / 384; n = rem % 384; KT = 12; boff = 0; }
    else if (rem < 204800) { rem -= 73728;  g = 1; kk = rem / 512; n = rem % 512; KT = 16; boff = 73728; }
    else                   { rem -= 204800; g = 2; kk = rem / 256; n = rem % 256; KT = 8;  boff = 204800; }

    int c = kk & 63, d = n & 127, ib = kk >> 6, ob = n >> 7;
    int w; float s = 1.0f;
    if (g == 0) {
        w = ib * 3 + ob;
    } else if (g == 1) {
        int i = ib & 1, o = ob & 1;
        bool ip = ib < 2, op = ob < 2;
        int base = 9 + i * 4 + o * 2;
        if (ip && op)        w = base;                   // +Wr
        else if (!ip && op)  { w = base + 1; s = -1.f; } // -Wi
        else if (ip && !op)  w = base + 1;               // +Wi
        else                 w = base;                   // +Wr
    } else {
        bool ip = (ib == 0), op = (ob == 0);
        if (ip && op)        w = 17;
        else if (!ip && op)  { w = 18; s = -1.f; }
        else if (ip && !op)  w = 18;
        else                 w = 17;
    }
    int widx = (w * 64 + c) * 128 + d;

    int kt = kk >> 4, k16 = kk & 15, n8 = n >> 3;
    int lane = (n & 7) * 4 + ((k16 & 7) >> 1);
    int slot = (k16 & 1) + ((k16 >> 3) << 1);
    int P = n8 >> 1, j = P >> 3, pp = P & 7;
    int blk = j * KT + kt;   // sequential step index within group
    int off = boff + ((blk * 8 + pp) * 32 + lane) * 8 + ((n8 & 1) << 2) + slot;

    dst[off] = __float2half(s * W[widx]);
}

// ---------------------------------------------------------------------------
__device__ __forceinline__ uint32_t s2u(const void* p) {
    uint32_t a;
    asm("{ .reg .u64 t; cvta.to.shared.u64 t, %1; cvt.u32.u64 %0, t; }" : "=r"(a) : "l"(p));
    return a;
}
#define CPA16(d, sp)  asm volatile("cp.async.cg.shared.global [%0], [%1], 16;" :: "r"(d), "l"(sp) : "memory")
#define CPA_COMMIT()  asm volatile("cp.async.commit_group;" ::: "memory")
#define CPA_WAIT2()   asm volatile("cp.async.wait_group 2;" ::: "memory")

#define MMA4(c, a, b0, b1) asm volatile( \
    "mma.sync.aligned.m16n8k16.row.col.f32.f16.f16.f32 " \
    "{%0,%1,%2,%3},{%4,%5,%6,%7},{%8,%9},{%0,%1,%2,%3};\n" \
    : "+f"((c)[0]), "+f"((c)[1]), "+f"((c)[2]), "+f"((c)[3]) \
    : "r"((a).x), "r"((a).y), "r"((a).z), "r"((a).w), "r"(b0), "r"(b1))

__device__ __forceinline__ void issue_step(uint32_t dst, const uint4* pq, const uint4* pk) {
    CPA16(dst,        pq);
    CPA16(dst + 512,  pq + 128);
    CPA16(dst + 1024, pk);
    CPA16(dst + 1536, pk + 128);
    CPA_COMMIT();
}

// ---------------------------------------------------------------------------
// Templated per-group body: conversion + fused GEMM with per-warp 3-ring.
// ---------------------------------------------------------------------------
template<int KT, int NPJ, int D, int IB0>
__device__ __forceinline__ void group_body(
    const float* __restrict__ xq, const float* __restrict__ xk, int E, int tileE,
    const uint4* __restrict__ Bq, const uint4* __restrict__ Bk,
    __half* sA, const uint4* wring, uint32_t wring_u32,
    int tid, int lane, int warpM, int warpN, float pre[2][2][2])
{
    __syncthreads();   // previous group's compute fully done before rewriting sA
    // ---- convert x slice -> fragment-major fp16 smem (64 edges) ----
    constexpr int DQ = D >> 2;
    constexpr int nq = 64 * DQ;
    #pragma unroll
    for (int t = 0; t < 2; ++t) {
        const float* x = t ? xk : xq;
        __half* A = sA + t * 16384;
        #pragma unroll 2
        for (int q0 = tid; q0 < nq; q0 += 256) {
            int el = q0 / DQ, c = (q0 % DQ) * 4;
            int ord = c_ord[IB0 + (c >> 6)];
            int e = tileE + el;
            float4 v = make_float4(0.f, 0.f, 0.f, 0.f);
            if (e < E) v = *(const float4*)(x + ((size_t)e * 9 + ord) * 64 + (c & 63));
            int r = el & 15, mtile = el >> 4;
            int kt = c >> 4, kk0 = c & 15;
            int ln0 = (r & 7) * 4 + ((kk0 & 7) >> 1);
            int hx  = (((kk0 >> 3) << 1) + (r >> 3)) * 2;
            int off = ((mtile * KT + kt) * 32 + ln0) * 8 + hx;
            *(__half2*)(A + off)     = __floats2half2_rn(v.x, v.y);
            *(__half2*)(A + off + 8) = __floats2half2_rn(v.z, v.w);
        }
    }
    __syncthreads();

    // ---- fused fp16 GEMMs + per-head q*k reduction ----
    const uint4* Aq = (const uint4*)sA;
    const uint4* Ak = Aq + 2048;
    const uint4* pq = Bq + warpN * 32 + lane;
    const uint4* pk = Bk + warpN * 32 + lane;

    // prologue: fill slots 0,1,2 (steps 0,1,2)
    issue_step(wring_u32,        pq, pk); pq += 256; pk += 256;
    issue_step(wring_u32 + 2048, pq, pk); pq += 256; pk += 256;
    issue_step(wring_u32 + 4096, pq, pk); pq += 256; pk += 256;

    int slot = 0;
    #pragma unroll 1
    for (int j = 0; j < NPJ; ++j) {
        float cq[2][2][2][4], ck[2][2][2][4];   // [np][mt][d2][4]
        #pragma unroll
        for (int a = 0; a < 2; a++)
            #pragma unroll
            for (int b = 0; b < 2; b++)
                #pragma unroll
                for (int d2 = 0; d2 < 2; d2++)
                    #pragma unroll
                    for (int i = 0; i < 4; i++) { cq[a][b][d2][i] = 0.f; ck[a][b][d2][i] = 0.f; }

        const uint4* a0 = Aq + (2 * warpM) * KT * 32 + lane;
        const uint4* a1 = a0 + KT * 32;
        const uint4* k0 = Ak + (2 * warpM) * KT * 32 + lane;
        const uint4* k1 = k0 + KT * 32;

        uint4 aqc0 = a0[0], aqc1 = a1[0], akc0 = k0[0], akc1 = k1[0];

        #pragma unroll 4
        for (int kt = 0; kt < KT; ++kt) {
            CPA_WAIT2();   // uniform: slot's data complete (always 3 in flight)

            const uint4* slotp = wring + (slot << 7);
            uint4 bq0 = slotp[lane],      bq1 = slotp[32 + lane];
            uint4 bk0 = slotp[64 + lane], bk1 = slotp[96 + lane];

            // unconditional refill (arrays padded; overrun harmless)
            issue_step(wring_u32 + (uint32_t)(slot << 11), pq, pk);
            pq += 256; pk += 256;

            // rotate A: load kt+1 (clamped at compile time) while consuming kt
            const int noff = (kt + 1 < KT) ? (kt + 1) * 32 : kt * 32;
            uint4 aqn0 = a0[noff], aqn1 = a1[noff];
            uint4 akn0 = k0[noff], akn1 = k1[noff];

            MMA4(cq[0][0][0], aqc0, bq0.x, bq0.y);
            MMA4(cq[0][0][1], aqc0, bq0.z, bq0.w);
            MMA4(cq[0][1][0], aqc1, bq0.x, bq0.y);
            MMA4(cq[0][1][1], aqc1, bq0.z, bq0.w);
            MMA4(cq[1][0][0], aqc0, bq1.x, bq1.y);
            MMA4(cq[1][0][1], aqc0, bq1.z, bq1.w);
            MMA4(cq[1][1][0], aqc1, bq1.x, bq1.y);
            MMA4(cq[1][1][1], aqc1, bq1.z, bq1.w);
            MMA4(ck[0][0][0], akc0, bk0.x, bk0.y);
            MMA4(ck[0][0][1], akc0, bk0.z, bk0.w);
            MMA4(ck[0][1][0], akc1, bk0.x, bk0.y);
            MMA4(ck[0][1][1], akc1, bk0.z, bk0.w);
            MMA4(ck[1][0][0], akc0, bk1.x, bk1.y);
            MMA4(ck[1][0][1], akc0, bk1.z, bk1.w);
            MMA4(ck[1][1][0], akc1, bk1.x, bk1.y);
            MMA4(ck[1][1][1], akc1, bk1.z, bk1.w);

            aqc0 = aqn0; aqc1 = aqn1; akc0 = akn0; akc1 = akn1;
            slot = (slot == 2) ? 0 : slot + 1;
        }
        #pragma unroll
        for (int np = 0; np < 2; ++np)
            #pragma unroll
            for (int mt = 0; mt < 2; ++mt) {
                pre[mt][0][np] += cq[np][mt][0][0] * ck[np][mt][0][0] + cq[np][mt][0][1] * ck[np][mt][0][1]
                                + cq[np][mt][1][0] * ck[np][mt][1][0] + cq[np][mt][1][1] * ck[np][mt][1][1];
                pre[mt][1][np] += cq[np][mt][0][2] * ck[np][mt][0][2] + cq[np][mt][0][3] * ck[np][mt][0][3]
                                + cq[np][mt][1][2] * ck[np][mt][1][2] + cq[np][mt][1][3] * ck[np][mt][1][3];
            }
    }
}

__global__ __launch_bounds__(256, 2)
void so2_attn_main(const float* __restrict__ xq, const float* __restrict__ xk, int E) {
    extern __shared__ __half sA[];   // [0]=q frags (16384 halfs), [16384]=k frags
    uint4* sB = (uint4*)(sA + 32768);        // per-warp rings: warp*384 + slot*128 uint4
    const int tid = threadIdx.x, lane = tid & 31, warp = tid >> 5;
    const int warpM = warp & 1, warpN = warp >> 1;
    const int tileE = blockIdx.x * 64;
    const uint32_t wring_u32 = s2u(sB) + ((warp * 384 + lane) << 4);
    const uint4* wring = sB + warp * 384;

    float pre[2][2][2];
    #pragma unroll
    for (int a = 0; a < 2; a++)
        #pragma unroll
        for (int b = 0; b < 2; b++)
            #pragma unroll
            for (int c = 0; c < 2; c++) pre[a][b][c] = 0.f;

    group_body<12, 3, 192, 0>(xq, xk, E, tileE, (const uint4*)g_Bq,
                              (const uint4*)g_Bk, sA, wring, wring_u32,
                              tid, lane, warpM, warpN, pre);
    group_body<16, 4, 256, 3>(xq, xk, E, tileE, (const uint4*)g_Bq + 9216,
                              (const uint4*)g_Bk + 9216, sA, wring, wring_u32,
                              tid, lane, warpM, warpN, pre);
    group_body< 8, 2, 128, 7>(xq, xk, E, tileE, (const uint4*)g_Bq + 25600,
                              (const uint4*)g_Bk + 25600, sA, wring, wring_u32,
                              tid, lane, warpM, warpN, pre);

    // reduce over the 4-lane n-split group and store pre (unique writer per (e,h))
    #pragma unroll
    for (int a = 0; a < 2; a++)
        #pragma unroll
        for (int b = 0; b < 2; b++)
            #pragma unroll
            for (int c = 0; c < 2; c++) {
                float v = pre[a][b][c];
                v += __shfl_xor_sync(0xffffffffu, v, 1);
                v += __shfl_xor_sync(0xffffffffu, v, 2);
                pre[a][b][c] = v;
            }
    if ((lane & 3) == 0) {
        int gID = lane >> 2;
        #pragma unroll
        for (int mt = 0; mt < 2; ++mt)
            #pragma unroll
            for (int rh = 0; rh < 2; ++rh)
                #pragma unroll
                for (int np = 0; np < 2; ++np) {
                    int e = tileE + (2 * warpM + mt) * 16 + gID + rh * 8;
                    int h = warpN + np * 4;
                    if (e < E) g_pre[e * 8 + h] = 0.25f * pre[mt][rh][np];
                }
    }
}

// ---------------------------------------------------------------------------
// Segment softmax
// ---------------------------------------------------------------------------
__device__ __forceinline__ unsigned fenc(float f) {
    unsigned b = __float_as_uint(f);
    return (b & 0x80000000u) ? ~b : (b | 0x80000000u);
}
__device__ __forceinline__ float fdec(unsigned u) {
    unsigned b = (u & 0x80000000u) ? (u & 0x7FFFFFFFu) : ~u;
    return __uint_as_float(b);
}

__global__ void k_init() {
    int i = blockIdx.x * blockDim.x + threadIdx.x;
    if (i < NODECAP * 8) { g_segmax[i] = 0u; g_segsum[i] = 0.f; }
}
__global__ void k_max(int E, const int* __restrict__ index) {
    int i = blockIdx.x * blockDim.x + threadIdx.x;
    if (i >= E * 8) return;
    int e = i >> 3, h = i & 7;
    atomicMax(&g_segmax[index[e] * 8 + h], fenc(g_pre[i]));
}
__global__ void k_exp(int E, const int* __restrict__ index, float* __restrict__ out) {
    int i = blockIdx.x * blockDim.x + threadIdx.x;
    if (i >= E * 8) return;
    int e = i >> 3, h = i & 7;
    int seg = index[e] * 8 + h;
    float ex = expf(g_pre[i] - fdec(g_segmax[seg]));
    out[i] = ex;
    atomicAdd(&g_segsum[seg], ex);
}
__global__ void k_norm(int E, const int* __restrict__ index, float* __restrict__ out) {
    int i = blockIdx.x * blockDim.x + threadIdx.x;
    if (i >= E * 8) return;
    int e = i >> 3, h = i & 7;
    out[i] = out[i] / (g_segsum[index[e] * 8 + h] + 1e-16f);
}

// ---------------------------------------------------------------------------
extern "C" void kernel_launch(void* const* d_in, const int* in_sizes, int n_in,
                              void* d_out, int out_size) {
    const float* xq    = (const float*)d_in[0];
    const float* xk    = (const float*)d_in[1];
    const float* Wq    = (const float*)d_in[2];
    const float* Wk    = (const float*)d_in[3];
    const int*   index = (const int*)d_in[4];
    float* out = (float*)d_out;
    int E = in_sizes[0] / (9 * 64);

    cudaFuncSetAttribute(so2_attn_main, cudaFuncAttributeMaxDynamicSharedMemorySize, SMEM_BYTES);

    __half* bq_dev = nullptr; __half* bk_dev = nullptr;
    cudaGetSymbolAddress((void**)&bq_dev, g_Bq);
    cudaGetSymbolAddress((void**)&bk_dev, g_Bk);

    // our launch idx 3 == global idx 5 (2 hidden harness launches) for ncu -s 5 -c 1
    prep_w<<<(G_TOTAL + 255) / 256, 256>>>(Wq, bq_dev);
    prep_w<<<(G_TOTAL + 255) / 256, 256>>>(Wk, bk_dev);
    k_init<<<(NODECAP * 8 + 255) / 256, 256>>>();

    so2_attn_main<<<(E + 63) / 64, 256, SMEM_BYTES>>>(xq, xk, E);

    int nb = (E * 8 + 255) / 256;
    k_max <<<nb, 256>>>(E, index);
    k_exp <<<nb, 256>>>(E, index, out);
    k_norm<<<nb, 256>>>(E, index, out);
}

// round 15
// speedup vs baseline: 1.3898x; 1.0415x over previous
#include <cuda_runtime.h>
#include <cuda_fp16.h>
#include <math.h>
#include <stdint.h>

#define NODECAP 16384
#define G_TOTAL 237568   // 192*384 + 256*512 + 128*256
#define BPAD    8192     // overrun pad: 3 steps x 256 uint4 x 8 halfs
#define PRECAP  (1<<20)
// smem: 64KB A + 24KB rings (8 warps x 3 x 1KB) + 16KB exchange (4 pairs x 4KB)
#define SMEM_BYTES 106496

__device__ __align__(16) __half g_Bq[G_TOTAL + BPAD];
__device__ __align__(16) __half g_Bk[G_TOTAL + BPAD];
__device__ float    g_pre[PRECAP];
__device__ unsigned g_segmax[NODECAP * 8];
__device__ float    g_segsum[NODECAP * 8];

__constant__ int c_ord[9] = {0, 2, 6, 3, 7, 1, 5, 8, 4};

// ---------------------------------------------------------------------------
// Weight prep: dense W_eff per |m| group (sign pattern folded), fp16,
// exact mma.m16n8k16 B-fragment order, (j,kt)-major contiguous blocks.
// ---------------------------------------------------------------------------
__global__ void prep_w(const float* __restrict__ W, __half* __restrict__ dst) {
    int idx = blockIdx.x * blockDim.x + threadIdx.x;
    if (idx >= G_TOTAL) return;
    int g, kk, n, KT, boff, rem = idx;
    if (rem < 73728)       { g = 0; kk = rem / 384; n = rem % 384; KT = 12; boff = 0; }
    else if (rem < 204800) { rem -= 73728;  g = 1; kk = rem / 512; n = rem % 512; KT = 16; boff = 73728; }
    else                   { rem -= 204800; g = 2; kk = rem / 256; n = rem % 256; KT = 8;  boff = 204800; }

    int c = kk & 63, d = n & 127, ib = kk >> 6, ob = n >> 7;
    int w; float s = 1.0f;
    if (g == 0) {
        w = ib * 3 + ob;
    } else if (g == 1) {
        int i = ib & 1, o = ob & 1;
        bool ip = ib < 2, op = ob < 2;
        int base = 9 + i * 4 + o * 2;
        if (ip && op)        w = base;                   // +Wr
        else if (!ip && op)  { w = base + 1; s = -1.f; } // -Wi
        else if (ip && !op)  w = base + 1;               // +Wi
        else                 w = base;                   // +Wr
    } else {
        bool ip = (ib == 0), op = (ob == 0);
        if (ip && op)        w = 17;
        else if (!ip && op)  { w = 18; s = -1.f; }
        else if (ip && !op)  w = 18;
        else                 w = 17;
    }
    int widx = (w * 64 + c) * 128 + d;

    int kt = kk >> 4, k16 = kk & 15, n8 = n >> 3;
    int lane = (n & 7) * 4 + ((k16 & 7) >> 1);
    int slot = (k16 & 1) + ((k16 >> 3) << 1);
    int P = n8 >> 1, j = P >> 3, pp = P & 7;
    int blk = j * KT + kt;   // sequential step index within group
    int off = boff + ((blk * 8 + pp) * 32 + lane) * 8 + ((n8 & 1) << 2) + slot;

    dst[off] = __float2half(s * W[widx]);
}

// ---------------------------------------------------------------------------
__device__ __forceinline__ uint32_t s2u(const void* p) {
    uint32_t a;
    asm("{ .reg .u64 t; cvta.to.shared.u64 t, %1; cvt.u32.u64 %0, t; }" : "=r"(a) : "l"(p));
    return a;
}
#define CPA16(d, sp)  asm volatile("cp.async.cg.shared.global [%0], [%1], 16;" :: "r"(d), "l"(sp) : "memory")
#define CPA_COMMIT()  asm volatile("cp.async.commit_group;" ::: "memory")
#define CPA_WAIT2()   asm volatile("cp.async.wait_group 2;" ::: "memory")
#define BARS(id)      asm volatile("bar.sync %0, 64;" :: "r"(id) : "memory")

#define MMA4(c, a, b0, b1) asm volatile( \
    "mma.sync.aligned.m16n8k16.row.col.f32.f16.f16.f32 " \
    "{%0,%1,%2,%3},{%4,%5,%6,%7},{%8,%9},{%0,%1,%2,%3};\n" \
    : "+f"((c)[0]), "+f"((c)[1]), "+f"((c)[2]), "+f"((c)[3]) \
    : "r"((a).x), "r"((a).y), "r"((a).z), "r"((a).w), "r"(b0), "r"(b1))

__device__ __forceinline__ void issue_step(uint32_t dst, const uint4* pm) {
    CPA16(dst,       pm);
    CPA16(dst + 512, pm + 128);
    CPA_COMMIT();
}

// ---------------------------------------------------------------------------
// Templated per-group body: conversion + warp-specialized (q|k) fused GEMM.
// ---------------------------------------------------------------------------
template<int KT, int NPJ, int D, int IB0>
__device__ __forceinline__ void group_body(
    const float* __restrict__ xq, const float* __restrict__ xk, int E, int tileE,
    const uint4* __restrict__ Bm,     // this warp's matrix (q or k), group base
    const uint4* __restrict__ As,     // this warp's A frags in smem (q or k)
    __half* sA, float* sX,            // sX: per-pair 4KB exchange buffer
    const uint4* wring, uint32_t wring_u32,
    int tid, int lane, int warpN, bool is_q, float pre[4][2][2])
{
    __syncthreads();   // previous group's compute fully done before rewriting sA
    // ---- convert x slice -> fragment-major fp16 smem (64 edges) ----
    constexpr int DQ = D >> 2;
    constexpr int nq = 64 * DQ;
    #pragma unroll
    for (int t = 0; t < 2; ++t) {
        const float* x = t ? xk : xq;
        __half* A = sA + t * 16384;
        #pragma unroll 2
        for (int q0 = tid; q0 < nq; q0 += 256) {
            int el = q0 / DQ, c = (q0 % DQ) * 4;
            int ord = c_ord[IB0 + (c >> 6)];
            int e = tileE + el;
            float4 v = make_float4(0.f, 0.f, 0.f, 0.f);
            if (e < E) v = *(const float4*)(x + ((size_t)e * 9 + ord) * 64 + (c & 63));
            int r = el & 15, mtile = el >> 4;
            int kt = c >> 4, kk0 = c & 15;
            int ln0 = (r & 7) * 4 + ((kk0 & 7) >> 1);
            int hx  = (((kk0 >> 3) << 1) + (r >> 3)) * 2;
            int off = ((mtile * KT + kt) * 32 + ln0) * 8 + hx;
            *(__half2*)(A + off)     = __floats2half2_rn(v.x, v.y);
            *(__half2*)(A + off + 8) = __floats2half2_rn(v.z, v.w);
        }
    }
    __syncthreads();

    // ---- warp-specialized GEMM (one matrix, m64 x n16 per warp) ----
    const uint4* pm = Bm + warpN * 32 + lane;
    const uint4* Al = As + lane;

    // prologue: fill ring slots 0,1,2
    issue_step(wring_u32,        pm); pm += 256;
    issue_step(wring_u32 + 1024, pm); pm += 256;
    issue_step(wring_u32 + 2048, pm); pm += 256;

    int slot = 0;
    #pragma unroll 1
    for (int j = 0; j < NPJ; ++j) {
        float c[2][4][2][4];   // [np][mt][d2][4]
        #pragma unroll
        for (int a = 0; a < 2; a++)
            #pragma unroll
            for (int b = 0; b < 4; b++)
                #pragma unroll
                for (int d2 = 0; d2 < 2; d2++)
                    #pragma unroll
                    for (int i = 0; i < 4; i++) c[a][b][d2][i] = 0.f;

        #pragma unroll 4
        for (int kt = 0; kt < KT; ++kt) {
            CPA_WAIT2();   // always 3 groups in flight; slot's data complete

            const uint4* slotp = wring + (slot << 6);
            uint4 b0 = slotp[lane], b1 = slotp[32 + lane];

            // unconditional refill (arrays padded; overrun harmless)
            issue_step(wring_u32 + (uint32_t)(slot << 10), pm);
            pm += 256;

            uint4 a0 = Al[(0 * KT + kt) * 32];
            uint4 a1 = Al[(1 * KT + kt) * 32];
            uint4 a2 = Al[(2 * KT + kt) * 32];
            uint4 a3 = Al[(3 * KT + kt) * 32];

            MMA4(c[0][0][0], a0, b0.x, b0.y);
            MMA4(c[0][0][1], a0, b0.z, b0.w);
            MMA4(c[0][1][0], a1, b0.x, b0.y);
            MMA4(c[0][1][1], a1, b0.z, b0.w);
            MMA4(c[0][2][0], a2, b0.x, b0.y);
            MMA4(c[0][2][1], a2, b0.z, b0.w);
            MMA4(c[0][3][0], a3, b0.x, b0.y);
            MMA4(c[0][3][1], a3, b0.z, b0.w);
            MMA4(c[1][0][0], a0, b1.x, b1.y);
            MMA4(c[1][0][1], a0, b1.z, b1.w);
            MMA4(c[1][1][0], a1, b1.x, b1.y);
            MMA4(c[1][1][1], a1, b1.z, b1.w);
            MMA4(c[1][2][0], a2, b1.x, b1.y);
            MMA4(c[1][2][1], a2, b1.z, b1.w);
            MMA4(c[1][3][0], a3, b1.x, b1.y);
            MMA4(c[1][3][1], a3, b1.z, b1.w);

            slot = (slot == 2) ? 0 : slot + 1;
        }

        // ---- per-j epilogue: exchange k-warp's C, q-warp accumulates ----
        #pragma unroll
        for (int np = 0; np < 2; ++np) {
            BARS(1 + warpN);              // q done reading previous chunk
            if (!is_q) {
                #pragma unroll
                for (int mt = 0; mt < 4; ++mt)
                    #pragma unroll
                    for (int d2 = 0; d2 < 2; ++d2)
                        #pragma unroll
                        for (int i = 0; i < 4; ++i)
                            sX[((mt * 8 + d2 * 4 + i) << 5) + lane] = c[np][mt][d2][i];
            }
            BARS(1 + warpN);              // chunk visible
            if (is_q) {
                #pragma unroll
                for (int mt = 0; mt < 4; ++mt)
                    #pragma unroll
                    for (int d2 = 0; d2 < 2; ++d2)
                        #pragma unroll
                        for (int i = 0; i < 4; ++i) {
                            float kv = sX[((mt * 8 + d2 * 4 + i) << 5) + lane];
                            pre[mt][i >> 1][np] += c[np][mt][d2][i] * kv;
                        }
            }
        }
    }
}

__global__ __launch_bounds__(256, 2)
void so2_attn_main(const float* __restrict__ xq, const float* __restrict__ xk, int E) {
    extern __shared__ __half sA[];   // [0]=Aq (16384 halfs), [16384]=Ak
    uint4* sB = (uint4*)(sA + 32768);            // rings: warp*192 uint4, slot*64
    float* sXbase = (float*)(sA + 45056);        // exchange: pair(warpN)*1024 floats
    const int tid = threadIdx.x, lane = tid & 31, warp = tid >> 5;
    const int warpN = warp & 3;
    const bool is_q = warp < 4;
    const int tileE = blockIdx.x * 64;
    const uint32_t wring_u32 = s2u(sB) + ((warp * 192 + lane) << 4);
    const uint4* wring = sB + warp * 192;
    float* sX = sXbase + warpN * 1024;

    const uint4* As = (const uint4*)sA + (is_q ? 0 : 2048);

    float pre[4][2][2];   // [mt][rowhalf][np]; head = warpN + np*4 (q-warps only)
    #pragma unroll
    for (int a = 0; a < 4; a++)
        #pragma unroll
        for (int b = 0; b < 2; b++)
            #pragma unroll
            for (int c = 0; c < 2; c++) pre[a][b][c] = 0.f;

    const uint4* Bq = (const uint4*)g_Bq;
    const uint4* Bk = (const uint4*)g_Bk;
    const uint4* Bm0 = is_q ? Bq : Bk;

    group_body<12, 3, 192, 0>(xq, xk, E, tileE, Bm0,         As, sA, sX, wring, wring_u32, tid, lane, warpN, is_q, pre);
    group_body<16, 4, 256, 3>(xq, xk, E, tileE, Bm0 + 9216,  As, sA, sX, wring, wring_u32, tid, lane, warpN, is_q, pre);
    group_body< 8, 2, 128, 7>(xq, xk, E, tileE, Bm0 + 25600, As, sA, sX, wring, wring_u32, tid, lane, warpN, is_q, pre);

    // q-warps: reduce over the 4-lane n-split group and store pre
    if (is_q) {
        #pragma unroll
        for (int a = 0; a < 4; a++)
            #pragma unroll
            for (int b = 0; b < 2; b++)
                #pragma unroll
                for (int c = 0; c < 2; c++) {
                    float v = pre[a][b][c];
                    v += __shfl_xor_sync(0xffffffffu, v, 1);
                    v += __shfl_xor_sync(0xffffffffu, v, 2);
                    pre[a][b][c] = v;
                }
        if ((lane & 3) == 0) {
            int gID = lane >> 2;
            #pragma unroll
            for (int mt = 0; mt < 4; ++mt)
                #pragma unroll
                for (int rh = 0; rh < 2; ++rh)
                    #pragma unroll
                    for (int np = 0; np < 2; ++np) {
                        int e = tileE + mt * 16 + gID + rh * 8;
                        int h = warpN + np * 4;
                        if (e < E) g_pre[e * 8 + h] = 0.25f * pre[mt][rh][np];
                    }
        }
    }
}

// ---------------------------------------------------------------------------
// Segment softmax
// ---------------------------------------------------------------------------
__device__ __forceinline__ unsigned fenc(float f) {
    unsigned b = __float_as_uint(f);
    return (b & 0x80000000u) ? ~b : (b | 0x80000000u);
}
__device__ __forceinline__ float fdec(unsigned u) {
    unsigned b = (u & 0x80000000u) ? (u & 0x7FFFFFFFu) : ~u;
    return __uint_as_float(b);
}

__global__ void k_init() {
    int i = blockIdx.x * blockDim.x + threadIdx.x;
    if (i < NODECAP * 8) { g_segmax[i] = 0u; g_segsum[i] = 0.f; }
}
__global__ void k_max(int E, const int* __restrict__ index) {
    int i = blockIdx.x * blockDim.x + threadIdx.x;
    if (i >= E * 8) return;
    int e = i >> 3, h = i & 7;
    atomicMax(&g_segmax[index[e] * 8 + h], fenc(g_pre[i]));
}
__global__ void k_exp(int E, const int* __restrict__ index, float* __restrict__ out) {
    int i = blockIdx.x * blockDim.x + threadIdx.x;
    if (i >= E * 8) return;
    int e = i >> 3, h = i & 7;
    int seg = index[e] * 8 + h;
    float ex = expf(g_pre[i] - fdec(g_segmax[seg]));
    out[i] = ex;
    atomicAdd(&g_segsum[seg], ex);
}
__global__ void k_norm(int E, const int* __restrict__ index, float* __restrict__ out) {
    int i = blockIdx.x * blockDim.x + threadIdx.x;
    if (i >= E * 8) return;
    int e = i >> 3, h = i & 7;
    out[i] = out[i] / (g_segsum[index[e] * 8 + h] + 1e-16f);
}

// ---------------------------------------------------------------------------
extern "C" void kernel_launch(void* const* d_in, const int* in_sizes, int n_in,
                              void* d_out, int out_size) {
    const float* xq    = (const float*)d_in[0];
    const float* xk    = (const float*)d_in[1];
    const float* Wq    = (const float*)d_in[2];
    const float* Wk    = (const float*)d_in[3];
    const int*   index = (const int*)d_in[4];
    float* out = (float*)d_out;
    int E = in_sizes[0] / (9 * 64);

    cudaFuncSetAttribute(so2_attn_main, cudaFuncAttributeMaxDynamicSharedMemorySize, SMEM_BYTES);

    __half* bq_dev = nullptr; __half* bk_dev = nullptr;
    cudaGetSymbolAddress((void**)&bq_dev, g_Bq);
    cudaGetSymbolAddress((void**)&bk_dev, g_Bk);

    // our launch idx 3 == global idx 5 (2 hidden harness launches) for ncu -s 5 -c 1
    prep_w<<<(G_TOTAL + 255) / 256, 256>>>(Wq, bq_dev);
    prep_w<<<(G_TOTAL + 255) / 256, 256>>>(Wk, bk_dev);
    k_init<<<(NODECAP * 8 + 255) / 256, 256>>>();

    so2_attn_main<<<(E + 63) / 64, 256, SMEM_BYTES>>>(xq, xk, E);

    int nb = (E * 8 + 255) / 256;
    k_max <<<nb, 256>>>(E, index);
    k_exp <<<nb, 256>>>(E, index, out);
    k_norm<<<nb, 256>>>(E, index, out);
}

// round 16
// speedup vs baseline: 1.4386x; 1.0351x over previous
#include <cuda_runtime.h>
#include <cuda_fp16.h>
#include <math.h>
#include <stdint.h>

#define NODECAP 16384
#define G_TOTAL 237568   // 192*384 + 256*512 + 128*256
#define BPAD    8192     // overrun pad (halfs): 2 steps x 256 uint4 x 8 halfs = 4096, 2x slack
#define PRECAP  (1<<20)
// smem: 64KB A frags + 16KB exchange (4 pairs x 4KB)
#define SMEM_BYTES 81920

__device__ __align__(16) __half g_Bq[G_TOTAL + BPAD];
__device__ __align__(16) __half g_Bk[G_TOTAL + BPAD];
__device__ float    g_pre[PRECAP];
__device__ unsigned g_segmax[NODECAP * 8];
__device__ float    g_segsum[NODECAP * 8];

__constant__ int c_ord[9] = {0, 2, 6, 3, 7, 1, 5, 8, 4};

// ---------------------------------------------------------------------------
// Weight prep: dense W_eff per |m| group (sign pattern folded), fp16,
// exact mma.m16n8k16 B-fragment order, (j,kt)-major contiguous blocks.
// ---------------------------------------------------------------------------
__global__ void prep_w(const float* __restrict__ W, __half* __restrict__ dst) {
    int idx = blockIdx.x * blockDim.x + threadIdx.x;
    if (idx >= G_TOTAL) return;
    int g, kk, n, KT, boff, rem = idx;
    if (rem < 73728)       { g = 0; kk = rem / 384; n = rem % 384; KT = 12; boff = 0; }
    else if (rem < 204800) { rem -= 73728;  g = 1; kk = rem / 512; n = rem % 512; KT = 16; boff = 73728; }
    else                   { rem -= 204800; g = 2; kk = rem / 256; n = rem % 256; KT = 8;  boff = 204800; }

    int c = kk & 63, d = n & 127, ib = kk >> 6, ob = n >> 7;
    int w; float s = 1.0f;
    if (g == 0) {
        w = ib * 3 + ob;
    } else if (g == 1) {
        int i = ib & 1, o = ob & 1;
        bool ip = ib < 2, op = ob < 2;
        int base = 9 + i * 4 + o * 2;
        if (ip && op)        w = base;                   // +Wr
        else if (!ip && op)  { w = base + 1; s = -1.f; } // -Wi
        else if (ip && !op)  w = base + 1;               // +Wi
        else                 w = base;                   // +Wr
    } else {
        bool ip = (ib == 0), op = (ob == 0);
        if (ip && op)        w = 17;
        else if (!ip && op)  { w = 18; s = -1.f; }
        else if (ip && !op)  w = 18;
        else                 w = 17;
    }
    int widx = (w * 64 + c) * 128 + d;

    int kt = kk >> 4, k16 = kk & 15, n8 = n >> 3;
    int lane = (n & 7) * 4 + ((k16 & 7) >> 1);
    int slot = (k16 & 1) + ((k16 >> 3) << 1);
    int P = n8 >> 1, j = P >> 3, pp = P & 7;
    int blk = j * KT + kt;   // sequential step index within group
    int off = boff + ((blk * 8 + pp) * 32 + lane) * 8 + ((n8 & 1) << 2) + slot;

    dst[off] = __float2half(s * W[widx]);
}

// ---------------------------------------------------------------------------
#define BARS(id) asm volatile("bar.sync %0, 64;" :: "r"(id) : "memory")

#define MMA4(c, a, b0, b1) asm volatile( \
    "mma.sync.aligned.m16n8k16.row.col.f32.f16.f16.f32 " \
    "{%0,%1,%2,%3},{%4,%5,%6,%7},{%8,%9},{%0,%1,%2,%3};\n" \
    : "+f"((c)[0]), "+f"((c)[1]), "+f"((c)[2]), "+f"((c)[3]) \
    : "r"((a).x), "r"((a).y), "r"((a).z), "r"((a).w), "r"(b0), "r"(b1))

// ---------------------------------------------------------------------------
// Templated per-group body: conversion + warp-specialized (q|k) fused GEMM.
// B streamed by direct LDG.128 with register rotation at distance 2.
// ---------------------------------------------------------------------------
template<int KT, int NPJ, int D, int IB0>
__device__ __forceinline__ void group_body(
    const float* __restrict__ xq, const float* __restrict__ xk, int E, int tileE,
    const uint4* __restrict__ Bm,     // this warp's matrix (q or k), group base
    const uint4* __restrict__ As,     // this warp's A frags in smem (q or k)
    __half* sA, float* sX,            // sX: per-pair 4KB exchange buffer
    int tid, int lane, int warpN, bool is_q, float pre[4][2][2])
{
    __syncthreads();   // previous group's compute fully done before rewriting sA
    // ---- convert x slice -> fragment-major fp16 smem (64 edges) ----
    constexpr int DQ = D >> 2;
    constexpr int nq = 64 * DQ;
    #pragma unroll
    for (int t = 0; t < 2; ++t) {
        const float* x = t ? xk : xq;
        __half* A = sA + t * 16384;
        #pragma unroll 2
        for (int q0 = tid; q0 < nq; q0 += 256) {
            int el = q0 / DQ, c = (q0 % DQ) * 4;
            int ord = c_ord[IB0 + (c >> 6)];
            int e = tileE + el;
            float4 v = make_float4(0.f, 0.f, 0.f, 0.f);
            if (e < E) v = *(const float4*)(x + ((size_t)e * 9 + ord) * 64 + (c & 63));
            int r = el & 15, mtile = el >> 4;
            int kt = c >> 4, kk0 = c & 15;
            int ln0 = (r & 7) * 4 + ((kk0 & 7) >> 1);
            int hx  = (((kk0 >> 3) << 1) + (r >> 3)) * 2;
            int off = ((mtile * KT + kt) * 32 + ln0) * 8 + hx;
            *(__half2*)(A + off)     = __floats2half2_rn(v.x, v.y);
            *(__half2*)(A + off + 8) = __floats2half2_rn(v.z, v.w);
        }
    }
    __syncthreads();

    // ---- warp-specialized GEMM (one matrix, m64 x n32 per warp-step) ----
    const uint4* Al = As + lane;
    const uint4* pm = Bm + warpN * 32 + lane;   // sequential cursor, +256/step

    // B register pipeline: current + next (distance 2 incl. in-flight LDG)
    uint4 b0c = pm[0], b1c = pm[128]; pm += 256;
    uint4 b0n = pm[0], b1n = pm[128]; pm += 256;

    #pragma unroll 1
    for (int j = 0; j < NPJ; ++j) {
        float c[2][4][2][4];   // [np][mt][d2][4]
        #pragma unroll
        for (int a = 0; a < 2; a++)
            #pragma unroll
            for (int b = 0; b < 4; b++)
                #pragma unroll
                for (int d2 = 0; d2 < 2; d2++)
                    #pragma unroll
                    for (int i = 0; i < 4; i++) c[a][b][d2][i] = 0.f;

        #pragma unroll 4
        for (int kt = 0; kt < KT; ++kt) {
            // issue LDG for step kt+2 (arrays padded; overrun harmless)
            uint4 b0nn = pm[0], b1nn = pm[128];
            pm += 256;

            uint4 a0 = Al[(0 * KT + kt) * 32];
            uint4 a1 = Al[(1 * KT + kt) * 32];
            uint4 a2 = Al[(2 * KT + kt) * 32];
            uint4 a3 = Al[(3 * KT + kt) * 32];

            MMA4(c[0][0][0], a0, b0c.x, b0c.y);
            MMA4(c[0][0][1], a0, b0c.z, b0c.w);
            MMA4(c[0][1][0], a1, b0c.x, b0c.y);
            MMA4(c[0][1][1], a1, b0c.z, b0c.w);
            MMA4(c[0][2][0], a2, b0c.x, b0c.y);
            MMA4(c[0][2][1], a2, b0c.z, b0c.w);
            MMA4(c[0][3][0], a3, b0c.x, b0c.y);
            MMA4(c[0][3][1], a3, b0c.z, b0c.w);
            MMA4(c[1][0][0], a0, b1c.x, b1c.y);
            MMA4(c[1][0][1], a0, b1c.z, b1c.w);
            MMA4(c[1][1][0], a1, b1c.x, b1c.y);
            MMA4(c[1][1][1], a1, b1c.z, b1c.w);
            MMA4(c[1][2][0], a2, b1c.x, b1c.y);
            MMA4(c[1][2][1], a2, b1c.z, b1c.w);
            MMA4(c[1][3][0], a3, b1c.x, b1c.y);
            MMA4(c[1][3][1], a3, b1c.z, b1c.w);

            b0c = b0n; b1c = b1n;
            b0n = b0nn; b1n = b1nn;
        }

        // ---- per-j epilogue: exchange k-warp's C, q-warp accumulates ----
        #pragma unroll
        for (int np = 0; np < 2; ++np) {
            BARS(1 + warpN);              // q done reading previous chunk
            if (!is_q) {
                #pragma unroll
                for (int mt = 0; mt < 4; ++mt)
                    #pragma unroll
                    for (int d2 = 0; d2 < 2; ++d2)
                        #pragma unroll
                        for (int i = 0; i < 4; ++i)
                            sX[((mt * 8 + d2 * 4 + i) << 5) + lane] = c[np][mt][d2][i];
            }
            BARS(1 + warpN);              // chunk visible
            if (is_q) {
                #pragma unroll
                for (int mt = 0; mt < 4; ++mt)
                    #pragma unroll
                    for (int d2 = 0; d2 < 2; ++d2)
                        #pragma unroll
                        for (int i = 0; i < 4; ++i) {
                            float kv = sX[((mt * 8 + d2 * 4 + i) << 5) + lane];
                            pre[mt][i >> 1][np] += c[np][mt][d2][i] * kv;
                        }
            }
        }
    }
}

__global__ __launch_bounds__(256, 2)
void so2_attn_main(const float* __restrict__ xq, const float* __restrict__ xk, int E) {
    extern __shared__ __half sA[];   // [0]=Aq (16384 halfs), [16384]=Ak
    float* sXbase = (float*)(sA + 32768);        // exchange: pair(warpN)*1024 floats
    const int tid = threadIdx.x, lane = tid & 31, warp = tid >> 5;
    const int warpN = warp & 3;
    const bool is_q = warp < 4;
    const int tileE = blockIdx.x * 64;
    float* sX = sXbase + warpN * 1024;

    const uint4* As = (const uint4*)sA + (is_q ? 0 : 2048);

    float pre[4][2][2];   // [mt][rowhalf][np]; head = warpN + np*4 (q-warps only)
    #pragma unroll
    for (int a = 0; a < 4; a++)
        #pragma unroll
        for (int b = 0; b < 2; b++)
            #pragma unroll
            for (int c = 0; c < 2; c++) pre[a][b][c] = 0.f;

    const uint4* Bm0 = is_q ? (const uint4*)g_Bq : (const uint4*)g_Bk;

    group_body<12, 3, 192, 0>(xq, xk, E, tileE, Bm0,         As, sA, sX, tid, lane, warpN, is_q, pre);
    group_body<16, 4, 256, 3>(xq, xk, E, tileE, Bm0 + 9216,  As, sA, sX, tid, lane, warpN, is_q, pre);
    group_body< 8, 2, 128, 7>(xq, xk, E, tileE, Bm0 + 25600, As, sA, sX, tid, lane, warpN, is_q, pre);

    // q-warps: reduce over the 4-lane n-split group and store pre
    if (is_q) {
        #pragma unroll
        for (int a = 0; a < 4; a++)
            #pragma unroll
            for (int b = 0; b < 2; b++)
                #pragma unroll
                for (int c = 0; c < 2; c++) {
                    float v = pre[a][b][c];
                    v += __shfl_xor_sync(0xffffffffu, v, 1);
                    v += __shfl_xor_sync(0xffffffffu, v, 2);
                    pre[a][b][c] = v;
                }
        if ((lane & 3) == 0) {
            int gID = lane >> 2;
            #pragma unroll
            for (int mt = 0; mt < 4; ++mt)
                #pragma unroll
                for (int rh = 0; rh < 2; ++rh)
                    #pragma unroll
                    for (int np = 0; np < 2; ++np) {
                        int e = tileE + mt * 16 + gID + rh * 8;
                        int h = warpN + np * 4;
                        if (e < E) g_pre[e * 8 + h] = 0.25f * pre[mt][rh][np];
                    }
        }
    }
}

// ---------------------------------------------------------------------------
// Segment softmax
// ---------------------------------------------------------------------------
__device__ __forceinline__ unsigned fenc(float f) {
    unsigned b = __float_as_uint(f);
    return (b & 0x80000000u) ? ~b : (b | 0x80000000u);
}
__device__ __forceinline__ float fdec(unsigned u) {
    unsigned b = (u & 0x80000000u) ? (u & 0x7FFFFFFFu) : ~u;
    return __uint_as_float(b);
}

__global__ void k_init() {
    int i = blockIdx.x * blockDim.x + threadIdx.x;
    if (i < NODECAP * 8) { g_segmax[i] = 0u; g_segsum[i] = 0.f; }
}
__global__ void k_max(int E, const int* __restrict__ index) {
    int i = blockIdx.x * blockDim.x + threadIdx.x;
    if (i >= E * 8) return;
    int e = i >> 3, h = i & 7;
    atomicMax(&g_segmax[index[e] * 8 + h], fenc(g_pre[i]));
}
__global__ void k_exp(int E, const int* __restrict__ index, float* __restrict__ out) {
    int i = blockIdx.x * blockDim.x + threadIdx.x;
    if (i >= E * 8) return;
    int e = i >> 3, h = i & 7;
    int seg = index[e] * 8 + h;
    float ex = expf(g_pre[i] - fdec(g_segmax[seg]));
    out[i] = ex;
    atomicAdd(&g_segsum[seg], ex);
}
__global__ void k_norm(int E, const int* __restrict__ index, float* __restrict__ out) {
    int i = blockIdx.x * blockDim.x + threadIdx.x;
    if (i >= E * 8) return;
    int e = i >> 3, h = i & 7;
    out[i] = out[i] / (g_segsum[index[e] * 8 + h] + 1e-16f);
}

// ---------------------------------------------------------------------------
extern "C" void kernel_launch(void* const* d_in, const int* in_sizes, int n_in,
                              void* d_out, int out_size) {
    const float* xq    = (const float*)d_in[0];
    const float* xk    = (const float*)d_in[1];
    const float* Wq    = (const float*)d_in[2];
    const float* Wk    = (const float*)d_in[3];
    const int*   index = (const int*)d_in[4];
    float* out = (float*)d_out;
    int E = in_sizes[0] / (9 * 64);

    cudaFuncSetAttribute(so2_attn_main, cudaFuncAttributeMaxDynamicSharedMemorySize, SMEM_BYTES);

    __half* bq_dev = nullptr; __half* bk_dev = nullptr;
    cudaGetSymbolAddress((void**)&bq_dev, g_Bq);
    cudaGetSymbolAddress((void**)&bk_dev, g_Bk);

    // our launch idx 3 == global idx 5 (2 hidden harness launches) for ncu -s 5 -c 1
    prep_w<<<(G_TOTAL + 255) / 256, 256>>>(Wq, bq_dev);
    prep_w<<<(G_TOTAL + 255) / 256, 256>>>(Wk, bk_dev);
    k_init<<<(NODECAP * 8 + 255) / 256, 256>>>();

    so2_attn_main<<<(E + 63) / 64, 256, SMEM_BYTES>>>(xq, xk, E);

    int nb = (E * 8 + 255) / 256;
    k_max <<<nb, 256>>>(E, index);
    k_exp <<<nb, 256>>>(E, index, out);
    k_norm<<<nb, 256>>>(E, index, out);
}

// round 17
// speedup vs baseline: 1.4559x; 1.0120x over previous
#include <cuda_runtime.h>
#include <cuda_fp16.h>
#include <math.h>
#include <stdint.h>

#define NODECAP 16384
#define G_TOTAL 237568   // 192*384 + 256*512 + 128*256
#define BPAD    8192     // overrun pad (halfs) for B cursor
#define PRECAP  (1<<20)
// smem: 64KB A frags + 32KB exchange (4 pairs x 8KB)
#define SMEM_BYTES 98304

__device__ __align__(16) __half g_Bq[G_TOTAL + BPAD];
__device__ __align__(16) __half g_Bk[G_TOTAL + BPAD];
__device__ float    g_pre[PRECAP];
__device__ unsigned g_segmax[NODECAP * 8];
__device__ float    g_segsum[NODECAP * 8];

__constant__ int c_ord[9] = {0, 2, 6, 3, 7, 1, 5, 8, 4};

// ---------------------------------------------------------------------------
// Weight prep: dense W_eff per |m| group (sign pattern folded), fp16,
// exact mma.m16n8k16 B-fragment order, (j,kt)-major contiguous blocks.
// ---------------------------------------------------------------------------
__global__ void prep_w(const float* __restrict__ W, __half* __restrict__ dst) {
    int idx = blockIdx.x * blockDim.x + threadIdx.x;
    if (idx >= G_TOTAL) return;
    int g, kk, n, KT, boff, rem = idx;
    if (rem < 73728)       { g = 0; kk = rem / 384; n = rem % 384; KT = 12; boff = 0; }
    else if (rem < 204800) { rem -= 73728;  g = 1; kk = rem / 512; n = rem % 512; KT = 16; boff = 73728; }
    else                   { rem -= 204800; g = 2; kk = rem / 256; n = rem % 256; KT = 8;  boff = 204800; }

    int c = kk & 63, d = n & 127, ib = kk >> 6, ob = n >> 7;
    int w; float s = 1.0f;
    if (g == 0) {
        w = ib * 3 + ob;
    } else if (g == 1) {
        int i = ib & 1, o = ob & 1;
        bool ip = ib < 2, op = ob < 2;
        int base = 9 + i * 4 + o * 2;
        if (ip && op)        w = base;                   // +Wr
        else if (!ip && op)  { w = base + 1; s = -1.f; } // -Wi
        else if (ip && !op)  w = base + 1;               // +Wi
        else                 w = base;                   // +Wr
    } else {
        bool ip = (ib == 0), op = (ob == 0);
        if (ip && op)        w = 17;
        else if (!ip && op)  { w = 18; s = -1.f; }
        else if (ip && !op)  w = 18;
        else                 w = 17;
    }
    int widx = (w * 64 + c) * 128 + d;

    int kt = kk >> 4, k16 = kk & 15, n8 = n >> 3;
    int lane = (n & 7) * 4 + ((k16 & 7) >> 1);
    int slot = (k16 & 1) + ((k16 >> 3) << 1);
    int P = n8 >> 1, j = P >> 3, pp = P & 7;
    int blk = j * KT + kt;   // sequential step index within group
    int off = boff + ((blk * 8 + pp) * 32 + lane) * 8 + ((n8 & 1) << 2) + slot;

    dst[off] = __float2half(s * W[widx]);
}

// ---------------------------------------------------------------------------
#define BARS(id) asm volatile("bar.sync %0, 64;" :: "r"(id) : "memory")

#define MMA4(c, a, b0, b1) asm volatile( \
    "mma.sync.aligned.m16n8k16.row.col.f32.f16.f16.f32 " \
    "{%0,%1,%2,%3},{%4,%5,%6,%7},{%8,%9},{%0,%1,%2,%3};\n" \
    : "+f"((c)[0]), "+f"((c)[1]), "+f"((c)[2]), "+f"((c)[3]) \
    : "r"((a).x), "r"((a).y), "r"((a).z), "r"((a).w), "r"(b0), "r"(b1))

// ---------------------------------------------------------------------------
// Templated per-group body: conversion + warp-specialized (q|k) fused GEMM.
// B streamed by direct LDG.128 with register rotation at distance 2.
// Epilogue: single vectorized exchange per j (both np chunks, 2 barriers).
// ---------------------------------------------------------------------------
template<int KT, int NPJ, int D, int IB0>
__device__ __forceinline__ void group_body(
    const float* __restrict__ xq, const float* __restrict__ xk, int E, int tileE,
    const uint4* __restrict__ Bm,     // this warp's matrix (q or k), group base
    const uint4* __restrict__ As,     // this warp's A frags in smem (q or k)
    __half* sA, float* sX,            // sX: per-pair 8KB exchange buffer
    int tid, int lane, int warpN, bool is_q, float pre[4][2][2])
{
    __syncthreads();   // previous group's compute fully done before rewriting sA
    // ---- convert x slice -> fragment-major fp16 smem (64 edges) ----
    constexpr int DQ = D >> 2;
    constexpr int nq = 64 * DQ;
    #pragma unroll
    for (int t = 0; t < 2; ++t) {
        const float* x = t ? xk : xq;
        __half* A = sA + t * 16384;
        #pragma unroll 2
        for (int q0 = tid; q0 < nq; q0 += 256) {
            int el = q0 / DQ, c = (q0 % DQ) * 4;
            int ord = c_ord[IB0 + (c >> 6)];
            int e = tileE + el;
            float4 v = make_float4(0.f, 0.f, 0.f, 0.f);
            if (e < E) v = *(const float4*)(x + ((size_t)e * 9 + ord) * 64 + (c & 63));
            int r = el & 15, mtile = el >> 4;
            int kt = c >> 4, kk0 = c & 15;
            int ln0 = (r & 7) * 4 + ((kk0 & 7) >> 1);
            int hx  = (((kk0 >> 3) << 1) + (r >> 3)) * 2;
            int off = ((mtile * KT + kt) * 32 + ln0) * 8 + hx;
            *(__half2*)(A + off)     = __floats2half2_rn(v.x, v.y);
            *(__half2*)(A + off + 8) = __floats2half2_rn(v.z, v.w);
        }
    }
    __syncthreads();

    // ---- warp-specialized GEMM (one matrix, m64 x n32 per warp-step) ----
    const uint4* Al = As + lane;
    const uint4* pm = Bm + warpN * 32 + lane;   // sequential cursor, +256/step

    // B register pipeline: current + next (distance 2 incl. in-flight LDG)
    uint4 b0c = pm[0], b1c = pm[128]; pm += 256;
    uint4 b0n = pm[0], b1n = pm[128]; pm += 256;

    #pragma unroll 1
    for (int j = 0; j < NPJ; ++j) {
        float c[2][4][2][4];   // [np][mt][d2][4]
        #pragma unroll
        for (int a = 0; a < 2; a++)
            #pragma unroll
            for (int b = 0; b < 4; b++)
                #pragma unroll
                for (int d2 = 0; d2 < 2; d2++)
                    #pragma unroll
                    for (int i = 0; i < 4; i++) c[a][b][d2][i] = 0.f;

        #pragma unroll 4
        for (int kt = 0; kt < KT; ++kt) {
            // issue LDG for step kt+2 (arrays padded; overrun harmless)
            uint4 b0nn = pm[0], b1nn = pm[128];
            pm += 256;

            uint4 a0 = Al[(0 * KT + kt) * 32];
            uint4 a1 = Al[(1 * KT + kt) * 32];
            uint4 a2 = Al[(2 * KT + kt) * 32];
            uint4 a3 = Al[(3 * KT + kt) * 32];

            MMA4(c[0][0][0], a0, b0c.x, b0c.y);
            MMA4(c[0][0][1], a0, b0c.z, b0c.w);
            MMA4(c[0][1][0], a1, b0c.x, b0c.y);
            MMA4(c[0][1][1], a1, b0c.z, b0c.w);
            MMA4(c[0][2][0], a2, b0c.x, b0c.y);
            MMA4(c[0][2][1], a2, b0c.z, b0c.w);
            MMA4(c[0][3][0], a3, b0c.x, b0c.y);
            MMA4(c[0][3][1], a3, b0c.z, b0c.w);
            MMA4(c[1][0][0], a0, b1c.x, b1c.y);
            MMA4(c[1][0][1], a0, b1c.z, b1c.w);
            MMA4(c[1][1][0], a1, b1c.x, b1c.y);
            MMA4(c[1][1][1], a1, b1c.z, b1c.w);
            MMA4(c[1][2][0], a2, b1c.x, b1c.y);
            MMA4(c[1][2][1], a2, b1c.z, b1c.w);
            MMA4(c[1][3][0], a3, b1c.x, b1c.y);
            MMA4(c[1][3][1], a3, b1c.z, b1c.w);

            b0c = b0n; b1c = b1n;
            b0n = b0nn; b1n = b1nn;
        }

        // ---- per-j epilogue: single vectorized exchange (both np chunks) ----
        BARS(1 + warpN);      // q finished reading previous j's buffer
        if (!is_q) {
            #pragma unroll
            for (int np = 0; np < 2; ++np)
                #pragma unroll
                for (int mt = 0; mt < 4; ++mt)
                    #pragma unroll
                    for (int d2 = 0; d2 < 2; ++d2)
                        *(float4*)&sX[((((np << 3) + (mt << 1) + d2) << 5) + lane) << 2] =
                            make_float4(c[np][mt][d2][0], c[np][mt][d2][1],
                                        c[np][mt][d2][2], c[np][mt][d2][3]);
        }
        BARS(1 + warpN);      // chunk visible
        if (is_q) {
            #pragma unroll
            for (int np = 0; np < 2; ++np)
                #pragma unroll
                for (int mt = 0; mt < 4; ++mt)
                    #pragma unroll
                    for (int d2 = 0; d2 < 2; ++d2) {
                        float4 kv = *(const float4*)&sX[((((np << 3) + (mt << 1) + d2) << 5) + lane) << 2];
                        pre[mt][0][np] += c[np][mt][d2][0] * kv.x + c[np][mt][d2][1] * kv.y;
                        pre[mt][1][np] += c[np][mt][d2][2] * kv.z + c[np][mt][d2][3] * kv.w;
                    }
        }
    }
}

__global__ __launch_bounds__(256, 2)
void so2_attn_main(const float* __restrict__ xq, const float* __restrict__ xk, int E) {
    extern __shared__ __half sA[];   // [0]=Aq (16384 halfs), [16384]=Ak
    float* sXbase = (float*)(sA + 32768);        // exchange: pair(warpN)*2048 floats
    const int tid = threadIdx.x, lane = tid & 31, warp = tid >> 5;
    const int warpN = warp & 3;
    const bool is_q = warp < 4;
    const int tileE = blockIdx.x * 64;
    float* sX = sXbase + warpN * 2048;

    const uint4* As = (const uint4*)sA + (is_q ? 0 : 2048);

    float pre[4][2][2];   // [mt][rowhalf][np]; head = warpN + np*4 (q-warps only)
    #pragma unroll
    for (int a = 0; a < 4; a++)
        #pragma unroll
        for (int b = 0; b < 2; b++)
            #pragma unroll
            for (int c = 0; c < 2; c++) pre[a][b][c] = 0.f;

    const uint4* Bm0 = is_q ? (const uint4*)g_Bq : (const uint4*)g_Bk;

    group_body<12, 3, 192, 0>(xq, xk, E, tileE, Bm0,         As, sA, sX, tid, lane, warpN, is_q, pre);
    group_body<16, 4, 256, 3>(xq, xk, E, tileE, Bm0 + 9216,  As, sA, sX, tid, lane, warpN, is_q, pre);
    group_body< 8, 2, 128, 7>(xq, xk, E, tileE, Bm0 + 25600, As, sA, sX, tid, lane, warpN, is_q, pre);

    // q-warps: reduce over the 4-lane n-split group and store pre
    if (is_q) {
        #pragma unroll
        for (int a = 0; a < 4; a++)
            #pragma unroll
            for (int b = 0; b < 2; b++)
                #pragma unroll
                for (int c = 0; c < 2; c++) {
                    float v = pre[a][b][c];
                    v += __shfl_xor_sync(0xffffffffu, v, 1);
                    v += __shfl_xor_sync(0xffffffffu, v, 2);
                    pre[a][b][c] = v;
                }
        if ((lane & 3) == 0) {
            int gID = lane >> 2;
            #pragma unroll
            for (int mt = 0; mt < 4; ++mt)
                #pragma unroll
                for (int rh = 0; rh < 2; ++rh)
                    #pragma unroll
                    for (int np = 0; np < 2; ++np) {
                        int e = tileE + mt * 16 + gID + rh * 8;
                        int h = warpN + np * 4;
                        if (e < E) g_pre[e * 8 + h] = 0.25f * pre[mt][rh][np];
                    }
        }
    }
}

// ---------------------------------------------------------------------------
// Segment softmax
// ---------------------------------------------------------------------------
__device__ __forceinline__ unsigned fenc(float f) {
    unsigned b = __float_as_uint(f);
    return (b & 0x80000000u) ? ~b : (b | 0x80000000u);
}
__device__ __forceinline__ float fdec(unsigned u) {
    unsigned b = (u & 0x80000000u) ? (u & 0x7FFFFFFFu) : ~u;
    return __uint_as_float(b);
}

__global__ void k_init() {
    int i = blockIdx.x * blockDim.x + threadIdx.x;
    if (i < NODECAP * 8) { g_segmax[i] = 0u; g_segsum[i] = 0.f; }
}
__global__ void k_max(int E, const int* __restrict__ index) {
    int i = blockIdx.x * blockDim.x + threadIdx.x;
    if (i >= E * 8) return;
    int e = i >> 3, h = i & 7;
    atomicMax(&g_segmax[index[e] * 8 + h], fenc(g_pre[i]));
}
__global__ void k_exp(int E, const int* __restrict__ index, float* __restrict__ out) {
    int i = blockIdx.x * blockDim.x + threadIdx.x;
    if (i >= E * 8) return;
    int e = i >> 3, h = i & 7;
    int seg = index[e] * 8 + h;
    float ex = expf(g_pre[i] - fdec(g_segmax[seg]));
    out[i] = ex;
    atomicAdd(&g_segsum[seg], ex);
}
__global__ void k_norm(int E, const int* __restrict__ index, float* __restrict__ out) {
    int i = blockIdx.x * blockDim.x + threadIdx.x;
    if (i >= E * 8) return;
    int e = i >> 3, h = i & 7;
    out[i] = out[i] / (g_segsum[index[e] * 8 + h] + 1e-16f);
}

// ---------------------------------------------------------------------------
extern "C" void kernel_launch(void* const* d_in, const int* in_sizes, int n_in,
                              void* d_out, int out_size) {
    const float* xq    = (const float*)d_in[0];
    const float* xk    = (const float*)d_in[1];
    const float* Wq    = (const float*)d_in[2];
    const float* Wk    = (const float*)d_in[3];
    const int*   index = (const int*)d_in[4];
    float* out = (float*)d_out;
    int E = in_sizes[0] / (9 * 64);

    cudaFuncSetAttribute(so2_attn_main, cudaFuncAttributeMaxDynamicSharedMemorySize, SMEM_BYTES);

    __half* bq_dev = nullptr; __half* bk_dev = nullptr;
    cudaGetSymbolAddress((void**)&bq_dev, g_Bq);
    cudaGetSymbolAddress((void**)&bk_dev, g_Bk);

    // our launch idx 3 == global idx 5 (2 hidden harness launches) for ncu -s 5 -c 1
    prep_w<<<(G_TOTAL + 255) / 256, 256>>>(Wq, bq_dev);
    prep_w<<<(G_TOTAL + 255) / 256, 256>>>(Wk, bk_dev);
    k_init<<<(NODECAP * 8 + 255) / 256, 256>>>();

    so2_attn_main<<<(E + 63) / 64, 256, SMEM_BYTES>>>(xq, xk, E);

    int nb = (E * 8 + 255) / 256;
    k_max <<<nb, 256>>>(E, index);
    k_exp <<<nb, 256>>>(E, index, out);
    k_norm<<<nb, 256>>>(E, index, out);
}